// round 7
// baseline (speedup 1.0000x reference)
#include <cuda_runtime.h>
#include <math.h>

namespace {
constexpr int B = 16, T = 100, N = 128, D = 3;
constexpr int FRAMES = B * T;                 // 1600
constexpr int NIT = 8;                        // consecutive frames per block
constexpr int BLOCKS = FRAMES / NIT;          // 200 persistent blocks
constexpr int FD = N * D;                     // 384 floats per frame
constexpr float MIN_DIST = 0.05f;
constexpr float R2 = MIN_DIST * MIN_DIST;     // 0.0025
constexpr float R2_GUARD = R2 + 1e-4f;        // slack for expansion error
constexpr int EXT = 192;                      // 128 + 64 wrap replica
}

__device__ float g_pen[BLOCKS];
__device__ float g_work[BLOCKS];
__device__ float g_stab[BLOCKS];
__device__ float g_ke0[BLOCKS];
__device__ float g_ke1[BLOCKS];
__device__ unsigned int g_count;              // zero-init; self-resetting

__global__ __launch_bounds__(256, 4) void fused_kernel(
    const float* __restrict__ traj,
    const float* __restrict__ vel,
    const float* __restrict__ frc,
    float* __restrict__ out)
{
    const int tid  = threadIdx.x;
    const int i    = tid & 127;        // row index for mainloop
    const int half = tid >> 7;         // j-range half: 0 -> 1..32, 1 -> 33..64
    const bool low = (tid < 128);      // staging/IO threads (one point each)
    const int f0   = blockIdx.x * NIT;

    __shared__ __align__(16) float4 spos[2][EXT];   // double-buffered (x,y,z,|p|^2)

    // ---- prologue: low threads load frame f0 point + frame f0 forces ----
    float cx = 0.f, cy = 0.f, cz = 0.f;            // current positions (point i)
    float fx = 0.f, fy = 0.f, fz = 0.f;            // current forces  (point i)
    if (low) {
        const float* p = traj + (size_t)f0 * FD + 3 * i;
        cx = p[0]; cy = p[1]; cz = p[2];
        const float* ff = frc + (size_t)f0 * FD + 3 * i;
        fx = ff[0]; fy = ff[1]; fz = ff[2];
    }

    float penacc = 0.f, wrkacc = 0.f, stabacc = 0.f, ke0acc = 0.f, ke1acc = 0.f;
    int p = 0;                                     // smem buffer parity

    #pragma unroll 1
    for (int it = 0; it < NIT; ++it) {
        const int f = f0 + it;
        const int t = f % T;

        // ---- stage current frame into smem buffer p (registers -> STS.128) ----
        if (low) {
            float w = cx * cx + cy * cy + cz * cz;
            float4 v = make_float4(cx, cy, cz, w);
            spos[p][i] = v;
            if (i < 64) spos[p][128 + i] = v;
        }

        // ---- issue prefetch for frame f+1 (hidden behind mainloop) ----
        float nx = 0.f, ny = 0.f, nz = 0.f;
        float gx = 0.f, gy = 0.f, gz = 0.f;
        if (low && f + 1 < FRAMES) {
            const float* pn = traj + (size_t)(f + 1) * FD + 3 * i;
            nx = pn[0]; ny = pn[1]; nz = pn[2];
            if (it + 1 < NIT) {
                const float* fn = frc + (size_t)(f + 1) * FD + 3 * i;
                gx = fn[0]; gy = fn[1]; gz = fn[2];
            }
        }

        __syncthreads();               // single barrier per frame

        // ---- penetration mainloop on smem buffer p ----
        const float4* P  = spos[p];
        const float4 me  = P[i];
        const float  mw  = me.w;
        const float  m2x = -2.0f * me.x;
        const float  m2y = -2.0f * me.y;
        const float  m2z = -2.0f * me.z;
        const int jbase = 1 + 32 * half;
        const float4* base = P + i + jbase;

        float accA = 1e30f, accB = 1e30f;
        #pragma unroll
        for (int jj = 0; jj < 32; ++jj) {
            float4 qq = base[jj];
            float d2 = mw + qq.w;
            d2 = fmaf(m2x, qq.x, d2);
            d2 = fmaf(m2y, qq.y, d2);
            d2 = fmaf(m2z, qq.z, d2);
            if (jj & 1) accB = fminf(accB, d2);
            else        accA = fminf(accA, d2);
        }
        if (fminf(accA, accB) < R2_GUARD) {     // rare exact slow path
            for (int jj = 0; jj < 32; ++jj) {
                float4 qq = base[jj];
                float dx = me.x - qq.x, dy = me.y - qq.y, dz = me.z - qq.z;
                float e2 = dx * dx + dy * dy + dz * dz;
                if (e2 < R2) {
                    float c = MIN_DIST - sqrtf(e2);
                    penacc += (jbase + jj == 64) ? 0.5f * c : c;
                }
            }
        }

        // ---- boundary frames: stability / kinetic (rare) ----
        if (low && (t == 0 || t >= T - 5)) {
            const float* pv = vel + (size_t)f * FD + 3 * i;
            float vx = pv[0], vy = pv[1], vz = pv[2];
            float v2 = vx * vx + vy * vy + vz * vz;
            if (t >= T - 5) {
                stabacc += sqrtf(v2);
                if (t == T - 1) ke1acc += 0.5f * v2;
            } else {
                ke0acc += 0.5f * v2;
            }
        }

        // ---- work term from pipeline registers ----
        if (low && t < T - 1) {
            wrkacc += fx * (nx - cx) + fy * (ny - cy) + fz * (nz - cz);
        }

        // roll the pipeline
        cx = nx; cy = ny; cz = nz;
        fx = gx; fy = gy; fz = gz;
        p ^= 1;
    }

    // ---- block reduction of 5 accumulators ----
    #pragma unroll
    for (int off = 16; off > 0; off >>= 1) {
        penacc  += __shfl_down_sync(0xffffffffu, penacc,  off);
        wrkacc  += __shfl_down_sync(0xffffffffu, wrkacc,  off);
        stabacc += __shfl_down_sync(0xffffffffu, stabacc, off);
        ke0acc  += __shfl_down_sync(0xffffffffu, ke0acc,  off);
        ke1acc  += __shfl_down_sync(0xffffffffu, ke1acc,  off);
    }
    __shared__ float sm[8][5];
    if ((tid & 31) == 0) {
        int w = tid >> 5;
        sm[w][0] = penacc; sm[w][1] = wrkacc; sm[w][2] = stabacc;
        sm[w][3] = ke0acc; sm[w][4] = ke1acc;
    }
    __syncthreads();
    if (tid == 0) {
        float sp = 0.f, sw = 0.f, ss = 0.f, s0v = 0.f, s1v = 0.f;
        #pragma unroll
        for (int w = 0; w < 8; ++w) {
            sp += sm[w][0]; sw += sm[w][1]; ss += sm[w][2];
            s0v += sm[w][3]; s1v += sm[w][4];
        }
        g_pen[blockIdx.x]  = sp;
        g_work[blockIdx.x] = sw;
        g_stab[blockIdx.x] = ss;
        g_ke0[blockIdx.x]  = s0v;
        g_ke1[blockIdx.x]  = s1v;
    }

    // ---- last-arriving block: deterministic final reduction ----
    __threadfence();
    __shared__ int is_last;
    if (tid == 0) {
        unsigned int old = atomicAdd(&g_count, 1u);
        is_last = (old == BLOCKS - 1) ? 1 : 0;
    }
    __syncthreads();
    if (!is_last) return;

    float pen_s = 0.f, wrk_s = 0.f, stab_s = 0.f, k0 = 0.f, k1 = 0.f;
    if (tid < BLOCKS) {
        pen_s  = g_pen[tid];
        wrk_s  = g_work[tid];
        stab_s = g_stab[tid];
        k0     = g_ke0[tid];
        k1     = g_ke1[tid];
    }
    #pragma unroll
    for (int off = 16; off > 0; off >>= 1) {
        pen_s  += __shfl_down_sync(0xffffffffu, pen_s,  off);
        wrk_s  += __shfl_down_sync(0xffffffffu, wrk_s,  off);
        stab_s += __shfl_down_sync(0xffffffffu, stab_s, off);
        k0     += __shfl_down_sync(0xffffffffu, k0,     off);
        k1     += __shfl_down_sync(0xffffffffu, k1,     off);
    }
    if ((tid & 31) == 0) {
        int w = tid >> 5;
        sm[w][0] = pen_s; sm[w][1] = wrk_s; sm[w][2] = stab_s;
        sm[w][3] = k0;    sm[w][4] = k1;
    }
    __syncthreads();
    if (tid == 0) {
        float sp = 0.f, sw = 0.f, ss = 0.f, s0v = 0.f, s1v = 0.f;
        #pragma unroll
        for (int w = 0; w < 8; ++w) {
            sp += sm[w][0]; sw += sm[w][1]; ss += sm[w][2];
            s0v += sm[w][3]; s1v += sm[w][4];
        }
        const float pen_loss  = sp / (float)B / ((float)T * (float)N * (float)(N - 1) * 0.5f);
        const float work_mean = sw / (float)(B * (T - 1) * N);
        const float stab_mean = ss / (float)(B * 5 * N);
        const float ks        = s0v / (float)(B * N);
        const float ke_       = s1v / (float)(B * N);
        out[0] = 10.0f * pen_loss + stab_mean + 0.1f * fabsf(ke_ - ks - work_mean);
        g_count = 0u;   // self-reset for next graph replay
    }
}

extern "C" void kernel_launch(void* const* d_in, const int* in_sizes, int n_in,
                              void* d_out, int out_size)
{
    const float* traj = (const float*)d_in[0];
    const float* vel  = (const float*)d_in[1];
    const float* frc  = (const float*)d_in[2];

    fused_kernel<<<BLOCKS, 256>>>(traj, vel, frc, (float*)d_out);
}

// round 8
// speedup vs baseline: 1.3414x; 1.3414x over previous
#include <cuda_runtime.h>
#include <math.h>

namespace {
constexpr int B = 16, T = 100, N = 128, D = 3;
constexpr int FRAMES = B * T;                 // 1600
constexpr int NIT = 4;                        // frames per block
constexpr int BLOCKS = FRAMES / NIT;          // 400
constexpr int FD = N * D;                     // 384 floats per frame
constexpr int F4 = FD / 4;                    // 96 float4 per frame
constexpr float MIN_DIST = 0.05f;
constexpr float R2 = MIN_DIST * MIN_DIST;     // 0.0025
constexpr float R2_GUARD = R2 + 1e-4f;        // slack for expansion error
constexpr int EXT = 192;                      // 128 + 64 wrap replica
}

__device__ float g_pen[BLOCKS];
__device__ float g_work[BLOCKS];
__device__ float g_stab[BLOCKS];
__device__ float g_ke0[BLOCKS];
__device__ float g_ke1[BLOCKS];
__device__ unsigned int g_count;              // zero-init; self-resetting

__global__ __launch_bounds__(256) void fused_kernel(
    const float* __restrict__ traj,
    const float* __restrict__ vel,
    const float* __restrict__ frc,
    float* __restrict__ out)
{
    const int tid = threadIdx.x;
    const int f0  = blockIdx.x * NIT;

    __shared__ __align__(16) float4 sP[NIT][EXT];       // (x,y,z,|p|^2) + replica
    __shared__ __align__(16) float  sT[(NIT + 1) * FD]; // raw traj: 5 frames
    __shared__ __align__(16) float  sF[NIT * FD];       // raw frc: 4 frames

    // ================= phase 1: one bulk LDG burst, max MLP =================
    {
        const float4* t4 = reinterpret_cast<const float4*>(traj);
        const float4* f4 = reinterpret_cast<const float4*>(frc);
        float4* dT = reinterpret_cast<float4*>(sT);
        float4* dF = reinterpret_cast<float4*>(sF);
        const int baseT = f0 * F4;
        // traj: 5 frames = 480 float4 (guard last block's lookahead frame)
        #pragma unroll
        for (int k = 0; k < 2; ++k) {
            int idx = tid + 256 * k;
            if (idx < (NIT + 1) * F4) {
                float4 v = (baseT + idx < FRAMES * F4) ? t4[baseT + idx]
                                                       : make_float4(0, 0, 0, 0);
                dT[idx] = v;
            }
        }
        // frc: 4 frames = 384 float4 (always in range)
        #pragma unroll
        for (int k = 0; k < 2; ++k) {
            int idx = tid + 256 * k;
            if (idx < NIT * F4) dF[idx] = f4[baseT + idx];
        }
    }
    __syncthreads();

    // ================= phase 2: build float4 frames + cheap terms ===========
    float penacc = 0.f, wrkacc = 0.f, stabacc = 0.f, ke0acc = 0.f, ke1acc = 0.f;

    #pragma unroll
    for (int k = 0; k < 2; ++k) {
        const int s  = tid + 256 * k;          // slot 0..511
        const int fl = s >> 7;                 // local frame 0..3
        const int p  = s & 127;                // point index
        const int t  = (f0 + fl) % T;

        const float x = sT[fl * FD + 3 * p];
        const float y = sT[fl * FD + 3 * p + 1];
        const float z = sT[fl * FD + 3 * p + 2];
        const float w = x * x + y * y + z * z;
        float4 v4 = make_float4(x, y, z, w);
        sP[fl][p] = v4;
        if (p < 64) sP[fl][128 + p] = v4;

        if (t < T - 1) {                       // work term from staged data
            const float nx = sT[(fl + 1) * FD + 3 * p];
            const float ny = sT[(fl + 1) * FD + 3 * p + 1];
            const float nz = sT[(fl + 1) * FD + 3 * p + 2];
            const float fx = sF[fl * FD + 3 * p];
            const float fy = sF[fl * FD + 3 * p + 1];
            const float fz = sF[fl * FD + 3 * p + 2];
            wrkacc += fx * (nx - x) + fy * (ny - y) + fz * (nz - z);
        }
        if (t == 0 || t >= T - 5) {            // rare boundary-frame vel terms
            const float* pv = vel + (size_t)(f0 + fl) * FD + 3 * p;
            float vx = pv[0], vy = pv[1], vz = pv[2];
            float v2 = vx * vx + vy * vy + vz * vz;
            if (t >= T - 5) {
                stabacc += sqrtf(v2);
                if (t == T - 1) ke1acc += 0.5f * v2;
            } else {
                ke0acc += 0.5f * v2;
            }
        }
    }
    __syncthreads();

    // ================= phase 3: 4 mainloop frames, zero gmem, zero syncs ====
    const int i    = tid & 127;
    const int half = tid >> 7;
    const int jbase = 1 + 32 * half;

    #pragma unroll 1
    for (int it = 0; it < NIT; ++it) {
        const float4* P  = sP[it];
        const float4 me  = P[i];
        const float  mw  = me.w;
        const float  m2x = -2.0f * me.x;
        const float  m2y = -2.0f * me.y;
        const float  m2z = -2.0f * me.z;
        const float4* base = P + i + jbase;

        float accA = 1e30f, accB = 1e30f;
        #pragma unroll
        for (int jj = 0; jj < 32; ++jj) {
            float4 qq = base[jj];
            float d2 = mw + qq.w;
            d2 = fmaf(m2x, qq.x, d2);
            d2 = fmaf(m2y, qq.y, d2);
            d2 = fmaf(m2z, qq.z, d2);
            if (jj & 1) accB = fminf(accB, d2);
            else        accA = fminf(accA, d2);
        }
        if (fminf(accA, accB) < R2_GUARD) {    // rare exact slow path
            for (int jj = 0; jj < 32; ++jj) {
                float4 qq = base[jj];
                float dx = me.x - qq.x, dy = me.y - qq.y, dz = me.z - qq.z;
                float e2 = dx * dx + dy * dy + dz * dz;
                if (e2 < R2) {
                    float c = MIN_DIST - sqrtf(e2);
                    penacc += (jbase + jj == 64) ? 0.5f * c : c;
                }
            }
        }
    }

    // ================= block reduction of 5 accumulators ====================
    #pragma unroll
    for (int off = 16; off > 0; off >>= 1) {
        penacc  += __shfl_down_sync(0xffffffffu, penacc,  off);
        wrkacc  += __shfl_down_sync(0xffffffffu, wrkacc,  off);
        stabacc += __shfl_down_sync(0xffffffffu, stabacc, off);
        ke0acc  += __shfl_down_sync(0xffffffffu, ke0acc,  off);
        ke1acc  += __shfl_down_sync(0xffffffffu, ke1acc,  off);
    }
    __shared__ float sm[8][5];
    if ((tid & 31) == 0) {
        int w = tid >> 5;
        sm[w][0] = penacc; sm[w][1] = wrkacc; sm[w][2] = stabacc;
        sm[w][3] = ke0acc; sm[w][4] = ke1acc;
    }
    __syncthreads();
    if (tid == 0) {
        float sp = 0.f, sw = 0.f, ss = 0.f, s0v = 0.f, s1v = 0.f;
        #pragma unroll
        for (int w = 0; w < 8; ++w) {
            sp += sm[w][0]; sw += sm[w][1]; ss += sm[w][2];
            s0v += sm[w][3]; s1v += sm[w][4];
        }
        g_pen[blockIdx.x]  = sp;
        g_work[blockIdx.x] = sw;
        g_stab[blockIdx.x] = ss;
        g_ke0[blockIdx.x]  = s0v;
        g_ke1[blockIdx.x]  = s1v;
    }

    // ================= last block: deterministic final reduction ============
    __threadfence();
    __shared__ int is_last;
    if (tid == 0) {
        unsigned int old = atomicAdd(&g_count, 1u);
        is_last = (old == BLOCKS - 1) ? 1 : 0;
    }
    __syncthreads();
    if (!is_last) return;

    float pen_s = 0.f, wrk_s = 0.f, stab_s = 0.f, k0 = 0.f, k1 = 0.f;
    #pragma unroll
    for (int q = tid; q < BLOCKS; q += 256) {
        pen_s  += g_pen[q];
        wrk_s  += g_work[q];
        stab_s += g_stab[q];
        k0     += g_ke0[q];
        k1     += g_ke1[q];
    }
    #pragma unroll
    for (int off = 16; off > 0; off >>= 1) {
        pen_s  += __shfl_down_sync(0xffffffffu, pen_s,  off);
        wrk_s  += __shfl_down_sync(0xffffffffu, wrk_s,  off);
        stab_s += __shfl_down_sync(0xffffffffu, stab_s, off);
        k0     += __shfl_down_sync(0xffffffffu, k0,     off);
        k1     += __shfl_down_sync(0xffffffffu, k1,     off);
    }
    if ((tid & 31) == 0) {
        int w = tid >> 5;
        sm[w][0] = pen_s; sm[w][1] = wrk_s; sm[w][2] = stab_s;
        sm[w][3] = k0;    sm[w][4] = k1;
    }
    __syncthreads();
    if (tid == 0) {
        float sp = 0.f, sw = 0.f, ss = 0.f, s0v = 0.f, s1v = 0.f;
        #pragma unroll
        for (int w = 0; w < 8; ++w) {
            sp += sm[w][0]; sw += sm[w][1]; ss += sm[w][2];
            s0v += sm[w][3]; s1v += sm[w][4];
        }
        const float pen_loss  = sp / (float)B / ((float)T * (float)N * (float)(N - 1) * 0.5f);
        const float work_mean = sw / (float)(B * (T - 1) * N);
        const float stab_mean = ss / (float)(B * 5 * N);
        const float ks        = s0v / (float)(B * N);
        const float ke_       = s1v / (float)(B * N);
        out[0] = 10.0f * pen_loss + stab_mean + 0.1f * fabsf(ke_ - ks - work_mean);
        g_count = 0u;   // self-reset for next graph replay
    }
}

extern "C" void kernel_launch(void* const* d_in, const int* in_sizes, int n_in,
                              void* d_out, int out_size)
{
    const float* traj = (const float*)d_in[0];
    const float* vel  = (const float*)d_in[1];
    const float* frc  = (const float*)d_in[2];

    fused_kernel<<<BLOCKS, 256>>>(traj, vel, frc, (float*)d_out);
}